// round 1
// baseline (speedup 1.0000x reference)
#include <cuda_runtime.h>
#include <cstdint>

#define THREADS 256

// ---------------------------------------------------------------------------
// Fused LSTM cell:
//   preact = [x|h|s|t] @ [Wx;Wh;Ws;Wt] + b_h   (B x 2048, K = 1024)
//   gates -> c_new = f*c + i*cg ; h_new = tanh(o*c_new)
// One CTA computes a 128-row x 32-hidden-col tile (= 128x128 preact tile
// covering all 4 gates), so the epilogue is register-local per thread.
// GEMM via mma.sync.m16n8k8 tf32 (cvt.rna), double-buffered smem pipeline.
// ---------------------------------------------------------------------------

__device__ __forceinline__ uint32_t f2tf32(float f) {
    uint32_t u;
    asm("cvt.rna.tf32.f32 %0, %1;" : "=r"(u) : "f"(f));
    return u;
}

__device__ __forceinline__ void mma_tf32(float* d, const uint32_t* a,
                                         uint32_t b0, uint32_t b1) {
    asm volatile(
        "mma.sync.aligned.m16n8k8.row.col.f32.tf32.tf32.f32 "
        "{%0,%1,%2,%3}, {%4,%5,%6,%7}, {%8,%9}, {%0,%1,%2,%3};\n"
        : "+f"(d[0]), "+f"(d[1]), "+f"(d[2]), "+f"(d[3])
        : "r"(a[0]), "r"(a[1]), "r"(a[2]), "r"(a[3]), "r"(b0), "r"(b1));
}

__device__ __forceinline__ float fast_sigmoid(float v) {
    return 1.0f / (1.0f + __expf(-v));
}

__device__ __forceinline__ float fast_tanh(float v) {
    float x = fminf(fmaxf(v, -20.0f), 20.0f);
    float e = __expf(2.0f * x);
    return (e - 1.0f) / (e + 1.0f);
}

// smem layout (padded strides for conflict-free fragment loads):
//   As: [2][128 rows][stride 20]  (K-chunk 16 -> cols 0..15 used)
//   Bs: [2][16 k][stride 136]     (128 N-cols used: col = gate*32 + jj)
__global__ __launch_bounds__(THREADS)
void lstm_fused_tf32(const float* __restrict__ x,  const float* __restrict__ hin,
                     const float* __restrict__ cin, const float* __restrict__ sp,
                     const float* __restrict__ tp,
                     const float* __restrict__ Wx, const float* __restrict__ Wh,
                     const float* __restrict__ bh, const float* __restrict__ Ws,
                     const float* __restrict__ Wt,
                     float* __restrict__ out, int B)
{
    __shared__ __align__(16) uint32_t As[2][128 * 20];
    __shared__ __align__(16) uint32_t Bs[2][16 * 136];

    const int tid  = threadIdx.x;
    const int warp = tid >> 5;
    const int lane = tid & 31;
    const int gid  = lane >> 2;   // group id 0..7
    const int tig  = lane & 3;    // thread-in-group 0..3
    const int m0   = blockIdx.x * 128;
    const int j0   = blockIdx.y * 32;

    float acc[16][4];
#pragma unroll
    for (int n = 0; n < 16; n++)
#pragma unroll
        for (int q = 0; q < 4; q++) acc[n][q] = 0.0f;

    uint32_t ra[2][4];
    uint32_t rb[2][4];

    // Global -> register loader for K-chunk `chunk` (16 k's, single segment
    // since all segment boundaries 256/768/896 are multiples of 16).
    auto load_chunk = [&](int chunk) {
        const int k = chunk * 16;
        const float* ap; int astr; int kl;
        if (k < 256)      { ap = x;   astr = 256; kl = k;       }
        else if (k < 768) { ap = hin; astr = 512; kl = k - 256; }
        else if (k < 896) { ap = sp;  astr = 128; kl = k - 768; }
        else              { ap = tp;  astr = 128; kl = k - 896; }
        const float* wp;
        if (k < 256)      wp = Wx + (size_t)kl * 2048;
        else if (k < 768) wp = Wh + (size_t)kl * 2048;
        else if (k < 896) wp = Ws + (size_t)kl * 2048;
        else              wp = Wt + (size_t)kl * 2048;

#pragma unroll
        for (int i = 0; i < 2; i++) {
            const int v = tid + i * 256;           // 0..511
            // A tile: 128 rows x 16 k  (512 float4)
            const int row = v >> 2, kq = v & 3;
            const float4 fa = *reinterpret_cast<const float4*>(
                ap + (size_t)(m0 + row) * astr + kl + kq * 4);
            ra[i][0] = f2tf32(fa.x); ra[i][1] = f2tf32(fa.y);
            ra[i][2] = f2tf32(fa.z); ra[i][3] = f2tf32(fa.w);
            // B tile: 16 k x 128 cols (col = gate*32 + jj), 512 float4
            const int kk = v >> 5, cq = v & 31;
            const int gate = cq >> 3, jj = (cq & 7) * 4;
            const float4 fb = *reinterpret_cast<const float4*>(
                wp + (size_t)kk * 2048 + gate * 512 + j0 + jj);
            rb[i][0] = f2tf32(fb.x); rb[i][1] = f2tf32(fb.y);
            rb[i][2] = f2tf32(fb.z); rb[i][3] = f2tf32(fb.w);
        }
    };

    auto store_chunk = [&](int buf) {
#pragma unroll
        for (int i = 0; i < 2; i++) {
            const int v = tid + i * 256;
            const int row = v >> 2, kq = v & 3;
            *reinterpret_cast<uint4*>(&As[buf][row * 20 + kq * 4]) =
                make_uint4(ra[i][0], ra[i][1], ra[i][2], ra[i][3]);
            const int kk = v >> 5, cq = v & 31;
            *reinterpret_cast<uint4*>(&Bs[buf][kk * 136 + cq * 4]) =
                make_uint4(rb[i][0], rb[i][1], rb[i][2], rb[i][3]);
        }
    };

    auto compute = [&](int buf) {
#pragma unroll
        for (int kk = 0; kk < 2; kk++) {
            const int ko = kk * 8;
            uint32_t a[4];
            const int rbase = warp * 16;
            a[0] = As[buf][(rbase + gid)     * 20 + ko + tig];
            a[1] = As[buf][(rbase + gid + 8) * 20 + ko + tig];
            a[2] = As[buf][(rbase + gid)     * 20 + ko + tig + 4];
            a[3] = As[buf][(rbase + gid + 8) * 20 + ko + tig + 4];
#pragma unroll
            for (int n = 0; n < 16; n++) {
                const uint32_t b0 = Bs[buf][(ko + tig)     * 136 + n * 8 + gid];
                const uint32_t b1 = Bs[buf][(ko + tig + 4) * 136 + n * 8 + gid];
                mma_tf32(acc[n], a, b0, b1);
            }
        }
    };

    // -------- main pipeline over K = 1024 (64 chunks of 16) --------
    load_chunk(0);
#pragma unroll 1
    for (int s = 0; s < 64; s++) {
        const int buf = s & 1;
        store_chunk(buf);
        __syncthreads();
        if (s < 63) load_chunk(s + 1);
        compute(buf);
        __syncthreads();
    }

    // -------- epilogue: gates + cell update, register-local --------
    // acc[n][*] covers preact cols [8n, 8n+8); gate g = n>>2, m = n&3.
    // C-fragment: idx 0:(row gid,   col 2tig), 1:(gid,   2tig+1)
    //             idx 2:(row gid+8, col 2tig), 3:(gid+8, 2tig+1)
    const int r0 = m0 + warp * 16 + gid;
#pragma unroll
    for (int m = 0; m < 4; m++) {
#pragma unroll
        for (int q = 0; q < 2; q++) {
            const int j = j0 + 8 * m + 2 * tig + q;
            const float bi = bh[j];
            const float bf = bh[512 + j];
            const float bo = bh[1024 + j];
            const float bc = bh[1536 + j];
#pragma unroll
            for (int rh = 0; rh < 2; rh++) {
                const int row = r0 + rh * 8;
                const int idx = 2 * rh + q;
                const float pi = acc[0  + m][idx] + bi;
                const float pf = acc[4  + m][idx] + bf;
                const float po = acc[8  + m][idx] + bo;
                const float pc = acc[12 + m][idx] + bc;
                const float ig = fast_sigmoid(pi);
                const float fg = fast_sigmoid(pf);
                const float og = fast_sigmoid(po);
                const float cg = fast_tanh(pc);
                const float cn = fg * cin[(size_t)row * 512 + j] + ig * cg;
                // output tuple: h_new [B,512] then c_new [B,512]
                out[(size_t)row * 512 + j] = fast_tanh(og * cn);
                out[(size_t)B * 512 + (size_t)row * 512 + j] = cn;
            }
        }
    }
}

extern "C" void kernel_launch(void* const* d_in, const int* in_sizes, int n_in,
                              void* d_out, int out_size) {
    const float* x  = (const float*)d_in[0];
    const float* h  = (const float*)d_in[1];
    const float* c  = (const float*)d_in[2];
    const float* sp = (const float*)d_in[3];
    const float* tp = (const float*)d_in[4];
    const float* Wx = (const float*)d_in[5];
    const float* Wh = (const float*)d_in[6];
    const float* bh = (const float*)d_in[7];
    const float* Ws = (const float*)d_in[8];
    const float* Wt = (const float*)d_in[9];
    float* out = (float*)d_out;

    const int B = in_sizes[0] / 256;   // x is [B, 256]
    dim3 grid(B / 128, 16);
    lstm_fused_tf32<<<grid, THREADS>>>(x, h, c, sp, tp, Wx, Wh, bh, Ws, Wt, out, B);
}